// round 3
// baseline (speedup 1.0000x reference)
#include <cuda_runtime.h>
#include <cstdint>

// Problem constants
constexpr int SEQ = 512;
constexpr int NB  = 64;     // batch
constexpr int NH  = 512;    // hidden per direction
constexpr int NI  = 1024;   // input features

// GEMM dims for xg precompute:  (SEQ*NB) x NI  @  NI x (2*3*NH)
constexpr int GM = SEQ * NB;     // 32768
constexpr int GK = NI;           // 1024
constexpr int GN = 2 * 3 * NH;   // 3072

// Recurrent kernel config
constexpr int RBLK = 128;        // persistent blocks (64 per direction), <= SM count
constexpr int COLS = 8;          // hidden columns per block
constexpr int RT   = 256;        // threads per block

// ---------------- device scratch (static, allocation-free) ----------------
__device__ float g_xg[(size_t)2 * SEQ * 3 * NB * NH];  // [d][s][g][b][h]  ~403MB
__device__ float g_hT [2][NH][NB];   // hidden state, [dir][feature][batch]
__device__ float g_rhT[2][NH][NB];   // r * h
__device__ float g_uT [2][NH][NB];   // update gate
__device__ unsigned g_bar_gen;
__device__ unsigned g_bar_cnt;

// ---------------- init: transpose initial_state into g_hT ----------------
__global__ void init_h_kernel(const float* __restrict__ init_state) {
    int i = blockIdx.x * blockDim.x + threadIdx.x;   // 2*NH*NB = 65536
    if (i < 2 * NH * NB) {
        int d = i / (NH * NB);
        int r = i % (NH * NB);
        int k = r / NB;
        int b = r % NB;
        g_hT[d][k][b] = init_state[(size_t)b * (2 * NH) + d * NH + k];
    }
}

// ---------------- xg precompute GEMM (fp32 SIMT, 128x128x8) ----------------
__global__ __launch_bounds__(256) void xg_gemm_kernel(
    const float* __restrict__ x,      // (SEQ,NB,NI) row-major = (GM, GK)
    const float* __restrict__ Wxf,    // (3, NI, NH)
    const float* __restrict__ Wxb)    // (3, NI, NH)
{
    __shared__ __align__(16) float As[8][128];
    __shared__ __align__(16) float Bs[8][128];

    const int bn = blockIdx.x;            // 0..23
    const int bm = blockIdx.y;            // 0..255
    const int n0 = bn * 128;
    const int d  = n0 / (3 * NH);
    const int rr = n0 % (3 * NH);
    const int g  = rr / NH;
    const int h0 = rr % NH;
    const float* W = (d == 0 ? Wxf : Wxb) + (size_t)g * GK * NH + h0;  // W[k][h], row stride NH
    const float* A = x + (size_t)bm * 128 * GK;

    const int tid  = threadIdx.x;
    const int arow = tid >> 1;
    const int aseg = (tid & 1) * 4;
    const int brow = tid >> 5;
    const int bcol = (tid & 31) * 4;
    const int tm   = (tid >> 4) * 8;
    const int tn   = (tid & 15) * 8;

    float acc[8][8];
    #pragma unroll
    for (int i = 0; i < 8; i++)
        #pragma unroll
        for (int j = 0; j < 8; j++) acc[i][j] = 0.f;

    for (int k0 = 0; k0 < GK; k0 += 8) {
        float4 av = *(const float4*)(A + (size_t)arow * GK + k0 + aseg);
        As[aseg + 0][arow] = av.x;
        As[aseg + 1][arow] = av.y;
        As[aseg + 2][arow] = av.z;
        As[aseg + 3][arow] = av.w;
        *(float4*)&Bs[brow][bcol] = *(const float4*)(W + (size_t)(k0 + brow) * NH + bcol);
        __syncthreads();
        #pragma unroll
        for (int kk = 0; kk < 8; kk++) {
            float4 a0 = *(const float4*)&As[kk][tm];
            float4 a1 = *(const float4*)&As[kk][tm + 4];
            float4 b0 = *(const float4*)&Bs[kk][tn];
            float4 b1 = *(const float4*)&Bs[kk][tn + 4];
            float af[8] = {a0.x, a0.y, a0.z, a0.w, a1.x, a1.y, a1.z, a1.w};
            float bf[8] = {b0.x, b0.y, b0.z, b0.w, b1.x, b1.y, b1.z, b1.w};
            #pragma unroll
            for (int i = 0; i < 8; i++)
                #pragma unroll
                for (int j = 0; j < 8; j++) acc[i][j] += af[i] * bf[j];
        }
        __syncthreads();
    }

    // write to g_xg[d][s][g][b][h]
    #pragma unroll
    for (int i = 0; i < 8; i++) {
        int m = bm * 128 + tm + i;
        int s = m >> 6;
        int b = m & 63;
        size_t base = ((((size_t)d * SEQ + s) * 3 + g) * NB + b) * NH + (h0 + tn);
        #pragma unroll
        for (int j = 0; j < 8; j += 4) {
            float4 v = make_float4(acc[i][j], acc[i][j+1], acc[i][j+2], acc[i][j+3]);
            *(float4*)&g_xg[base + j] = v;
        }
    }
}

// ---------------- grid barrier (all RBLK blocks resident) ----------------
__device__ __forceinline__ void grid_barrier(unsigned& gen) {
    __syncthreads();
    if (threadIdx.x == 0) {
        __threadfence();
        unsigned arrived = atomicAdd(&g_bar_cnt, 1u);
        if (arrived == RBLK - 1) {
            g_bar_cnt = 0;
            __threadfence();
            atomicAdd(&g_bar_gen, 1u);
        } else {
            while (*(volatile unsigned*)&g_bar_gen == gen) { __nanosleep(64); }
        }
        __threadfence();
        gen++;
    }
    __syncthreads();
}

// ---------------- persistent recurrent kernel ----------------
// smem layout (floats):
//   smh   [NH*NB]      = 32768   (h in phase1, r*h in phase2)  [k][b]
//   smwru [NH*16]      =  8192   (Wh_r | Wh_u columns)         [k][16]
//   smwc  [NH*8]       =  4096   (Wh_c columns)                [k][8]
//   smred [8192]                 (K-split partials)
//   smxg  [1024]                 (xg staging)                  [gc][b]
constexpr int OFF_WRU = NH * NB;            // 32768
constexpr int OFF_WC  = OFF_WRU + NH * 16;  // 40960
constexpr int OFF_RED = OFF_WC + NH * 8;    // 45056
constexpr int OFF_XG  = OFF_RED + 8192;     // 53248
constexpr int SMEM_FLOATS = OFF_XG + 1024;  // 54272
constexpr int SMEM_BYTES  = SMEM_FLOATS * 4; // 217088

__device__ __forceinline__ float sigmoidf_(float x) {
    return 1.0f / (1.0f + __expf(-x));
}

__global__ __launch_bounds__(RT, 1) void gru_recurrent_kernel(
    const float* __restrict__ Whf, const float* __restrict__ Whb,
    const float* __restrict__ bf,  const float* __restrict__ bb,
    float* __restrict__ out)
{
    extern __shared__ __align__(16) float smbuf[];
    float* smh   = smbuf;
    float* smwru = smbuf + OFF_WRU;
    float* smwc  = smbuf + OFF_WC;
    float* smred = smbuf + OFF_RED;
    float* smxg  = smbuf + OFF_XG;

    const int bid = blockIdx.x;
    const int tid = threadIdx.x;
    const int d   = bid >> 6;           // direction
    const int c0  = (bid & 63) * COLS;  // hidden-column slice
    const float* Wh   = d ? Whb : Whf;
    const float* bias = d ? bb  : bf;

    // load weight slices once (persistent across all timesteps)
    for (int idx = tid; idx < NH * COLS; idx += RT) {
        int k = idx >> 3, j = idx & 7;
        smwru[k * 16 + j]       = Wh[(size_t)0 * NH * NH + (size_t)k * NH + c0 + j];
        smwru[k * 16 + 8 + j]   = Wh[(size_t)1 * NH * NH + (size_t)k * NH + c0 + j];
        smwc [k * 8 + j]        = Wh[(size_t)2 * NH * NH + (size_t)k * NH + c0 + j];
    }
    unsigned gen = *(volatile unsigned*)&g_bar_gen;

    for (int t = 0; t < SEQ; t++) {
        const int sx = d ? (SEQ - 1 - t) : t;
        const float* xg_step = g_xg + (size_t)((size_t)d * SEQ + sx) * 3 * NB * NH;

        // ---- phase 1: r, u gates ----
        {
            const float4* src = (const float4*)(&g_hT[d][0][0]);
            float4* dst = (float4*)smh;
            #pragma unroll 4
            for (int i = tid; i < NH * NB / 4; i += RT) dst[i] = __ldcg(&src[i]);
            // stage xg gates r,u for our columns: [gc][b]
            {
                int gb = tid >> 1;
                int g = gb >> 6, b = gb & 63, half = tid & 1;
                float4 v = *(const float4*)(xg_step + ((size_t)g * NB + b) * NH + c0 + half * 4);
                int gc = g * 8 + half * 4;
                smxg[(gc + 0) * 64 + b] = v.x;
                smxg[(gc + 1) * 64 + b] = v.y;
                smxg[(gc + 2) * 64 + b] = v.z;
                smxg[(gc + 3) * 64 + b] = v.w;
            }
        }
        __syncthreads();
        {
            // dots: 64b x 16gc output, K split in 8 slices of 64
            const int ks = tid >> 5;         // 0..7
            const int ln = tid & 31;
            const int b0 = (ln >> 2) * 8;    // 8 batch rows
            const int cq = ln & 3;           // 4 gate-cols
            float acc[8][4];
            #pragma unroll
            for (int i = 0; i < 8; i++)
                #pragma unroll
                for (int j = 0; j < 4; j++) acc[i][j] = 0.f;
            const int kb = ks * 64;
            #pragma unroll 4
            for (int k = kb; k < kb + 64; k++) {
                float4 h0 = *(const float4*)&smh[k * 64 + b0];
                float4 h1 = *(const float4*)&smh[k * 64 + b0 + 4];
                float4 w  = *(const float4*)&smwru[k * 16 + cq * 4];
                float hv[8] = {h0.x, h0.y, h0.z, h0.w, h1.x, h1.y, h1.z, h1.w};
                float wv[4] = {w.x, w.y, w.z, w.w};
                #pragma unroll
                for (int i = 0; i < 8; i++)
                    #pragma unroll
                    for (int j = 0; j < 4; j++) acc[i][j] += hv[i] * wv[j];
            }
            #pragma unroll
            for (int j = 0; j < 4; j++)
                #pragma unroll
                for (int i = 0; i < 8; i++)
                    smred[ks * 1024 + (cq * 4 + j) * 64 + (b0 + i)] = acc[i][j];
        }
        __syncthreads();
        for (int o = tid; o < 1024; o += RT) {
            float s = 0.f;
            #pragma unroll
            for (int q = 0; q < 8; q++) s += smred[q * 1024 + o];
            int gc = o >> 6, b = o & 63;
            int g = gc >> 3, j = gc & 7, col = c0 + j;
            float pre = s + smxg[gc * 64 + b] + bias[g * NH + col];
            float v = sigmoidf_(pre);
            if (g == 0) {
                __stcg(&g_rhT[d][col][b], v * smh[col * 64 + b]);
            } else {
                __stcg(&g_uT[d][col][b], v);
            }
        }
        grid_barrier(gen);

        // ---- phase 2: candidate + state update ----
        {
            const float4* src = (const float4*)(&g_rhT[d][0][0]);
            float4* dst = (float4*)smh;
            #pragma unroll 4
            for (int i = tid; i < NH * NB / 4; i += RT) dst[i] = __ldcg(&src[i]);
            if (tid < 128) {
                int b = tid >> 1, half = tid & 1;
                float4 v = *(const float4*)(xg_step + ((size_t)2 * NB + b) * NH + c0 + half * 4);
                int gc = half * 4;
                smxg[(gc + 0) * 64 + b] = v.x;
                smxg[(gc + 1) * 64 + b] = v.y;
                smxg[(gc + 2) * 64 + b] = v.z;
                smxg[(gc + 3) * 64 + b] = v.w;
            }
        }
        __syncthreads();
        {
            // dots: 64b x 8c output, K split in 16 slices of 32
            const int ks = tid >> 4;        // 0..15
            const int ln = tid & 15;
            const int b0 = (ln >> 1) * 8;
            const int cq = ln & 1;
            float acc[8][4];
            #pragma unroll
            for (int i = 0; i < 8; i++)
                #pragma unroll
                for (int j = 0; j < 4; j++) acc[i][j] = 0.f;
            const int kb = ks * 32;
            #pragma unroll 4
            for (int k = kb; k < kb + 32; k++) {
                float4 h0 = *(const float4*)&smh[k * 64 + b0];
                float4 h1 = *(const float4*)&smh[k * 64 + b0 + 4];
                float4 w  = *(const float4*)&smwc[k * 8 + cq * 4];
                float hv[8] = {h0.x, h0.y, h0.z, h0.w, h1.x, h1.y, h1.z, h1.w};
                float wv[4] = {w.x, w.y, w.z, w.w};
                #pragma unroll
                for (int i = 0; i < 8; i++)
                    #pragma unroll
                    for (int j = 0; j < 4; j++) acc[i][j] += hv[i] * wv[j];
            }
            #pragma unroll
            for (int j = 0; j < 4; j++)
                #pragma unroll
                for (int i = 0; i < 8; i++)
                    smred[ks * 512 + (cq * 4 + j) * 64 + (b0 + i)] = acc[i][j];
        }
        __syncthreads();
        {
            const int srow = d ? (SEQ - 1 - t) : t;
            for (int o = tid; o < 512; o += RT) {
                float s = 0.f;
                #pragma unroll
                for (int q = 0; q < 16; q++) s += smred[q * 512 + o];
                int j = o >> 6, b = o & 63, col = c0 + j;
                float pre = s + smxg[o] + bias[2 * NH + col];
                float c = tanhf(pre);
                float u = __ldcg(&g_uT[d][col][b]);
                float hold = __ldcg(&g_hT[d][col][b]);
                float hn = u * hold + (1.0f - u) * c;
                __stcg(&g_hT[d][col][b], hn);
                out[(size_t)srow * (NB * 2 * NH) + (size_t)b * (2 * NH) + d * NH + col] = hn;
                if (t == SEQ - 1) {
                    out[(size_t)SEQ * (NB * 2 * NH) + (size_t)b * (2 * NH) + d * NH + col] = hn;
                }
            }
        }
        grid_barrier(gen);
    }
}

// ---------------- launch ----------------
extern "C" void kernel_launch(void* const* d_in, const int* in_sizes, int n_in,
                              void* d_out, int out_size) {
    const float* x    = (const float*)d_in[0];
    const float* init = (const float*)d_in[1];
    const float* Wxf  = (const float*)d_in[2];
    const float* Whf  = (const float*)d_in[3];
    const float* bf   = (const float*)d_in[4];
    const float* Wxb  = (const float*)d_in[5];
    const float* Whb  = (const float*)d_in[6];
    const float* bb   = (const float*)d_in[7];
    float* out = (float*)d_out;

    cudaFuncSetAttribute(gru_recurrent_kernel,
                         cudaFuncAttributeMaxDynamicSharedMemorySize, SMEM_BYTES);

    init_h_kernel<<<(2 * NH * NB + 255) / 256, 256>>>(init);
    xg_gemm_kernel<<<dim3(GN / 128, GM / 128), 256>>>(x, Wxf, Wxb);
    gru_recurrent_kernel<<<RBLK, RT, SMEM_BYTES>>>(Whf, Whb, bf, bb, out);
}

// round 4
// speedup vs baseline: 1.2253x; 1.2253x over previous
#include <cuda_runtime.h>
#include <cstdint>

// Problem constants
constexpr int SEQ = 512;
constexpr int NB  = 64;     // batch
constexpr int NH  = 512;    // hidden per direction
constexpr int NI  = 1024;   // input features

// GEMM dims for xg precompute:  (SEQ*NB) x NI  @  NI x (2*3*NH)
constexpr int GM = SEQ * NB;     // 32768
constexpr int GK = NI;           // 1024
constexpr int GN = 2 * 3 * NH;   // 3072

// Recurrent kernel config
constexpr int RBLK = 128;        // persistent blocks (64 per direction), <= SM count
constexpr int COLS = 8;          // hidden columns per block
constexpr int RT   = 256;        // threads per block

// ---------------- device scratch (static, allocation-free) ----------------
__device__ float g_xg[(size_t)2 * SEQ * 3 * NB * NH];  // [d][s][g][b][h]  ~403MB
__device__ float g_hT [2][NH][NB];   // hidden state, [dir][feature][batch]
__device__ float g_rhT[2][NH][NB];   // r * h
__device__ float g_uT [2][NH][NB];   // update gate
__device__ unsigned g_bar_gen;
__device__ unsigned g_bar_cnt;

// ---------------- init: transpose initial_state into g_hT ----------------
__global__ void init_h_kernel(const float* __restrict__ init_state) {
    int i = blockIdx.x * blockDim.x + threadIdx.x;   // 2*NH*NB = 65536
    if (i < 2 * NH * NB) {
        int d = i / (NH * NB);
        int r = i % (NH * NB);
        int k = r / NB;
        int b = r % NB;
        g_hT[d][k][b] = init_state[(size_t)b * (2 * NH) + d * NH + k];
    }
}

// ---------------- tf32 helpers ----------------
__device__ __forceinline__ unsigned f2tf(float f) {
    unsigned u;
    asm("cvt.rna.tf32.f32 %0, %1;" : "=r"(u) : "f"(f));
    return u;
}

__device__ __forceinline__ void mma_tf32(float* c, const unsigned* a, const unsigned* b) {
    asm volatile(
        "mma.sync.aligned.m16n8k8.row.col.f32.tf32.tf32.f32 "
        "{%0,%1,%2,%3}, {%4,%5,%6,%7}, {%8,%9}, {%0,%1,%2,%3};"
        : "+f"(c[0]), "+f"(c[1]), "+f"(c[2]), "+f"(c[3])
        : "r"(a[0]), "r"(a[1]), "r"(a[2]), "r"(a[3]),
          "r"(b[0]), "r"(b[1]));
}

// ---------------- xg precompute GEMM (tf32 tensor-core, 128x128x32) ----------------
// 8 warps; warp computes 64x32 via 4x4 grid of m16n8k8 mma.
constexpr int KT = 32;
constexpr int AS_LD = 36;   // 32 + 4 pad, conflict-free fragment reads
constexpr int BS_LD = 132;  // 128 + 4 pad

__global__ __launch_bounds__(256, 2) void xg_gemm_tc(
    const float* __restrict__ x,      // (GM, GK) row-major
    const float* __restrict__ Wxf,    // (3, NI, NH)
    const float* __restrict__ Wxb)    // (3, NI, NH)
{
    __shared__ unsigned As[128][AS_LD];  // [m][k]
    __shared__ unsigned Bs[KT][BS_LD];   // [k][n]

    const int bn = blockIdx.x;            // 0..23
    const int bm = blockIdx.y;            // 0..255
    const int n0 = bn * 128;
    const int d  = n0 / (3 * NH);
    const int rr = n0 % (3 * NH);
    const int g  = rr / NH;
    const int h0 = rr % NH;
    const float* W = (d == 0 ? Wxf : Wxb) + (size_t)g * GK * NH + h0;  // W[k][h], row stride NH
    const float* A = x + (size_t)bm * 128 * GK;

    const int tid  = threadIdx.x;
    const int warp = tid >> 5;
    const int lane = tid & 31;
    const int wm = warp & 1;      // 0..1  (64-row half)
    const int wn = warp >> 1;     // 0..3  (32-col quarter)
    const int g4 = lane >> 2;     // 0..7
    const int tg = lane & 3;      // 0..3

    float c[4][4][4];
    #pragma unroll
    for (int mi = 0; mi < 4; mi++)
        #pragma unroll
        for (int ni = 0; ni < 4; ni++)
            #pragma unroll
            for (int q = 0; q < 4; q++) c[mi][ni][q] = 0.f;

    for (int k0 = 0; k0 < GK; k0 += KT) {
        // stage A tile 128x32 (4 float4 per thread), converting to tf32
        #pragma unroll
        for (int i = 0; i < 4; i++) {
            int slot = tid + i * 256;
            int row = slot >> 3, c4 = (slot & 7) * 4;
            float4 v = *(const float4*)(A + (size_t)row * GK + k0 + c4);
            As[row][c4 + 0] = f2tf(v.x);
            As[row][c4 + 1] = f2tf(v.y);
            As[row][c4 + 2] = f2tf(v.z);
            As[row][c4 + 3] = f2tf(v.w);
        }
        // stage B tile 32x128
        #pragma unroll
        for (int i = 0; i < 4; i++) {
            int slot = tid + i * 256;
            int kk = slot >> 5, c4 = (slot & 31) * 4;
            float4 v = *(const float4*)(W + (size_t)(k0 + kk) * NH + c4);
            Bs[kk][c4 + 0] = f2tf(v.x);
            Bs[kk][c4 + 1] = f2tf(v.y);
            Bs[kk][c4 + 2] = f2tf(v.z);
            Bs[kk][c4 + 3] = f2tf(v.w);
        }
        __syncthreads();

        #pragma unroll
        for (int ks = 0; ks < 4; ks++) {
            unsigned a[4][4], b[4][2];
            #pragma unroll
            for (int mi = 0; mi < 4; mi++) {
                int r = wm * 64 + mi * 16 + g4;
                int kc = ks * 8 + tg;
                a[mi][0] = As[r][kc];
                a[mi][1] = As[r + 8][kc];
                a[mi][2] = As[r][kc + 4];
                a[mi][3] = As[r + 8][kc + 4];
            }
            #pragma unroll
            for (int ni = 0; ni < 4; ni++) {
                int cc = wn * 32 + ni * 8 + g4;
                int kr = ks * 8 + tg;
                b[ni][0] = Bs[kr][cc];
                b[ni][1] = Bs[kr + 4][cc];
            }
            #pragma unroll
            for (int mi = 0; mi < 4; mi++)
                #pragma unroll
                for (int ni = 0; ni < 4; ni++)
                    mma_tf32(c[mi][ni], a[mi], b[ni]);
        }
        __syncthreads();
    }

    // epilogue: write to g_xg[d][s][g][b][h]
    #pragma unroll
    for (int mi = 0; mi < 4; mi++) {
        #pragma unroll
        for (int half = 0; half < 2; half++) {
            int m = bm * 128 + wm * 64 + mi * 16 + g4 + half * 8;
            int s = m >> 6;
            int b = m & 63;
            size_t base = ((((size_t)d * SEQ + s) * 3 + g) * NB + b) * NH
                        + (h0 + wn * 32);
            #pragma unroll
            for (int ni = 0; ni < 4; ni++) {
                int col = ni * 8 + 2 * tg;
                float2 v;
                v.x = c[mi][ni][half * 2 + 0];
                v.y = c[mi][ni][half * 2 + 1];
                *(float2*)&g_xg[base + col] = v;
            }
        }
    }
}

// ---------------- grid barrier (all RBLK blocks resident) ----------------
__device__ __forceinline__ void grid_barrier(unsigned& gen) {
    __syncthreads();
    if (threadIdx.x == 0) {
        __threadfence();
        unsigned arrived = atomicAdd(&g_bar_cnt, 1u);
        if (arrived == RBLK - 1) {
            g_bar_cnt = 0;
            __threadfence();
            atomicAdd(&g_bar_gen, 1u);
        } else {
            while (*(volatile unsigned*)&g_bar_gen == gen) { __nanosleep(64); }
        }
        __threadfence();
        gen++;
    }
    __syncthreads();
}

// ---------------- persistent recurrent kernel ----------------
constexpr int OFF_WRU = NH * NB;            // 32768
constexpr int OFF_WC  = OFF_WRU + NH * 16;  // 40960
constexpr int OFF_RED = OFF_WC + NH * 8;    // 45056
constexpr int OFF_XG  = OFF_RED + 8192;     // 53248
constexpr int SMEM_FLOATS = OFF_XG + 1024;  // 54272
constexpr int SMEM_BYTES  = SMEM_FLOATS * 4; // 217088

__device__ __forceinline__ float sigmoidf_(float x) {
    return 1.0f / (1.0f + __expf(-x));
}

__global__ __launch_bounds__(RT, 1) void gru_recurrent_kernel(
    const float* __restrict__ Whf, const float* __restrict__ Whb,
    const float* __restrict__ bf,  const float* __restrict__ bb,
    float* __restrict__ out)
{
    extern __shared__ __align__(16) float smbuf[];
    float* smh   = smbuf;
    float* smwru = smbuf + OFF_WRU;
    float* smwc  = smbuf + OFF_WC;
    float* smred = smbuf + OFF_RED;
    float* smxg  = smbuf + OFF_XG;

    const int bid = blockIdx.x;
    const int tid = threadIdx.x;
    const int d   = bid >> 6;           // direction
    const int c0  = (bid & 63) * COLS;  // hidden-column slice
    const float* Wh   = d ? Whb : Whf;
    const float* bias = d ? bb  : bf;

    // load weight slices once (persistent across all timesteps)
    for (int idx = tid; idx < NH * COLS; idx += RT) {
        int k = idx >> 3, j = idx & 7;
        smwru[k * 16 + j]       = Wh[(size_t)0 * NH * NH + (size_t)k * NH + c0 + j];
        smwru[k * 16 + 8 + j]   = Wh[(size_t)1 * NH * NH + (size_t)k * NH + c0 + j];
        smwc [k * 8 + j]        = Wh[(size_t)2 * NH * NH + (size_t)k * NH + c0 + j];
    }
    unsigned gen = *(volatile unsigned*)&g_bar_gen;

    for (int t = 0; t < SEQ; t++) {
        const int sx = d ? (SEQ - 1 - t) : t;
        const float* xg_step = g_xg + (size_t)((size_t)d * SEQ + sx) * 3 * NB * NH;

        // ---- phase 1: r, u gates ----
        {
            const float4* src = (const float4*)(&g_hT[d][0][0]);
            float4* dst = (float4*)smh;
            #pragma unroll 4
            for (int i = tid; i < NH * NB / 4; i += RT) dst[i] = __ldcg(&src[i]);
            // stage xg gates r,u for our columns: [gc][b]
            {
                int gb = tid >> 1;
                int g = gb >> 6, b = gb & 63, half = tid & 1;
                float4 v = *(const float4*)(xg_step + ((size_t)g * NB + b) * NH + c0 + half * 4);
                int gc = g * 8 + half * 4;
                smxg[(gc + 0) * 64 + b] = v.x;
                smxg[(gc + 1) * 64 + b] = v.y;
                smxg[(gc + 2) * 64 + b] = v.z;
                smxg[(gc + 3) * 64 + b] = v.w;
            }
        }
        __syncthreads();
        {
            // dots: 64b x 16gc output, K split in 8 slices of 64
            const int ks = tid >> 5;         // 0..7
            const int ln = tid & 31;
            const int b0 = (ln >> 2) * 8;    // 8 batch rows
            const int cq = ln & 3;           // 4 gate-cols
            float acc[8][4];
            #pragma unroll
            for (int i = 0; i < 8; i++)
                #pragma unroll
                for (int j = 0; j < 4; j++) acc[i][j] = 0.f;
            const int kb = ks * 64;
            #pragma unroll 4
            for (int k = kb; k < kb + 64; k++) {
                float4 h0 = *(const float4*)&smh[k * 64 + b0];
                float4 h1 = *(const float4*)&smh[k * 64 + b0 + 4];
                float4 w  = *(const float4*)&smwru[k * 16 + cq * 4];
                float hv[8] = {h0.x, h0.y, h0.z, h0.w, h1.x, h1.y, h1.z, h1.w};
                float wv[4] = {w.x, w.y, w.z, w.w};
                #pragma unroll
                for (int i = 0; i < 8; i++)
                    #pragma unroll
                    for (int j = 0; j < 4; j++) acc[i][j] += hv[i] * wv[j];
            }
            #pragma unroll
            for (int j = 0; j < 4; j++)
                #pragma unroll
                for (int i = 0; i < 8; i++)
                    smred[ks * 1024 + (cq * 4 + j) * 64 + (b0 + i)] = acc[i][j];
        }
        __syncthreads();
        for (int o = tid; o < 1024; o += RT) {
            float s = 0.f;
            #pragma unroll
            for (int q = 0; q < 8; q++) s += smred[q * 1024 + o];
            int gc = o >> 6, b = o & 63;
            int g = gc >> 3, j = gc & 7, col = c0 + j;
            float pre = s + smxg[gc * 64 + b] + bias[g * NH + col];
            float v = sigmoidf_(pre);
            if (g == 0) {
                __stcg(&g_rhT[d][col][b], v * smh[col * 64 + b]);
            } else {
                __stcg(&g_uT[d][col][b], v);
            }
        }
        grid_barrier(gen);

        // ---- phase 2: candidate + state update ----
        {
            const float4* src = (const float4*)(&g_rhT[d][0][0]);
            float4* dst = (float4*)smh;
            #pragma unroll 4
            for (int i = tid; i < NH * NB / 4; i += RT) dst[i] = __ldcg(&src[i]);
            if (tid < 128) {
                int b = tid >> 1, half = tid & 1;
                float4 v = *(const float4*)(xg_step + ((size_t)2 * NB + b) * NH + c0 + half * 4);
                int gc = half * 4;
                smxg[(gc + 0) * 64 + b] = v.x;
                smxg[(gc + 1) * 64 + b] = v.y;
                smxg[(gc + 2) * 64 + b] = v.z;
                smxg[(gc + 3) * 64 + b] = v.w;
            }
        }
        __syncthreads();
        {
            // dots: 64b x 8c output, K split in 16 slices of 32
            const int ks = tid >> 4;        // 0..15
            const int ln = tid & 15;
            const int b0 = (ln >> 1) * 8;
            const int cq = ln & 1;
            float acc[8][4];
            #pragma unroll
            for (int i = 0; i < 8; i++)
                #pragma unroll
                for (int j = 0; j < 4; j++) acc[i][j] = 0.f;
            const int kb = ks * 32;
            #pragma unroll 4
            for (int k = kb; k < kb + 32; k++) {
                float4 h0 = *(const float4*)&smh[k * 64 + b0];
                float4 h1 = *(const float4*)&smh[k * 64 + b0 + 4];
                float4 w  = *(const float4*)&smwc[k * 8 + cq * 4];
                float hv[8] = {h0.x, h0.y, h0.z, h0.w, h1.x, h1.y, h1.z, h1.w};
                float wv[4] = {w.x, w.y, w.z, w.w};
                #pragma unroll
                for (int i = 0; i < 8; i++)
                    #pragma unroll
                    for (int j = 0; j < 4; j++) acc[i][j] += hv[i] * wv[j];
            }
            #pragma unroll
            for (int j = 0; j < 4; j++)
                #pragma unroll
                for (int i = 0; i < 8; i++)
                    smred[ks * 512 + (cq * 4 + j) * 64 + (b0 + i)] = acc[i][j];
        }
        __syncthreads();
        {
            const int srow = d ? (SEQ - 1 - t) : t;
            for (int o = tid; o < 512; o += RT) {
                float s = 0.f;
                #pragma unroll
                for (int q = 0; q < 16; q++) s += smred[q * 512 + o];
                int j = o >> 6, b = o & 63, col = c0 + j;
                float pre = s + smxg[o] + bias[2 * NH + col];
                float c = tanhf(pre);
                float u = __ldcg(&g_uT[d][col][b]);
                float hold = __ldcg(&g_hT[d][col][b]);
                float hn = u * hold + (1.0f - u) * c;
                __stcg(&g_hT[d][col][b], hn);
                out[(size_t)srow * (NB * 2 * NH) + (size_t)b * (2 * NH) + d * NH + col] = hn;
                if (t == SEQ - 1) {
                    out[(size_t)SEQ * (NB * 2 * NH) + (size_t)b * (2 * NH) + d * NH + col] = hn;
                }
            }
        }
        grid_barrier(gen);
    }
}

// ---------------- launch ----------------
extern "C" void kernel_launch(void* const* d_in, const int* in_sizes, int n_in,
                              void* d_out, int out_size) {
    const float* x    = (const float*)d_in[0];
    const float* init = (const float*)d_in[1];
    const float* Wxf  = (const float*)d_in[2];
    const float* Whf  = (const float*)d_in[3];
    const float* bf   = (const float*)d_in[4];
    const float* Wxb  = (const float*)d_in[5];
    const float* Whb  = (const float*)d_in[6];
    const float* bb   = (const float*)d_in[7];
    float* out = (float*)d_out;

    cudaFuncSetAttribute(gru_recurrent_kernel,
                         cudaFuncAttributeMaxDynamicSharedMemorySize, SMEM_BYTES);

    init_h_kernel<<<(2 * NH * NB + 255) / 256, 256>>>(init);
    xg_gemm_tc<<<dim3(GN / 128, GM / 128), 256>>>(x, Wxf, Wxb);
    gru_recurrent_kernel<<<RBLK, RT, SMEM_BYTES>>>(Whf, Whb, bf, bb, out);
}

// round 11
// speedup vs baseline: 1.6513x; 1.3477x over previous
#include <cuda_runtime.h>
#include <cstdint>

// Problem constants
constexpr int SEQ = 512;
constexpr int NB  = 64;     // batch
constexpr int NH  = 512;    // hidden per direction
constexpr int NI  = 1024;   // input features

// GEMM dims for xg precompute
constexpr int GM = SEQ * NB;     // 32768
constexpr int GK = NI;           // 1024
constexpr int GN = 2 * 3 * NH;   // 3072

// Recurrent kernel config
constexpr int RBLK = 128;
constexpr int COLS = 8;
constexpr int RT   = 256;

// ---------------- device scratch ----------------
__device__ float g_xg[(size_t)2 * SEQ * 3 * NB * NH];  // [d][s][g][b][h]
__device__ float g_hTF [2][NB][NH];   // tf32-rounded h broadcast, [d][b][k]
__device__ float g_rhTF[2][NB][NH];   // tf32-rounded r*h broadcast
__device__ unsigned g_bar_gen;
__device__ unsigned g_bar_cnt;

// ---------------- tf32 helpers ----------------
__device__ __forceinline__ unsigned f2tf(float f) {
    unsigned u;
    asm("cvt.rna.tf32.f32 %0, %1;" : "=r"(u) : "f"(f));
    return u;
}
__device__ __forceinline__ float f2tf_f(float f) {
    unsigned u = f2tf(f);
    return __uint_as_float(u);
}

__device__ __forceinline__ void mma_tf32(float* c, const unsigned* a, const unsigned* b) {
    asm volatile(
        "mma.sync.aligned.m16n8k8.row.col.f32.tf32.tf32.f32 "
        "{%0,%1,%2,%3}, {%4,%5,%6,%7}, {%8,%9}, {%0,%1,%2,%3};"
        : "+f"(c[0]), "+f"(c[1]), "+f"(c[2]), "+f"(c[3])
        : "r"(a[0]), "r"(a[1]), "r"(a[2]), "r"(a[3]),
          "r"(b[0]), "r"(b[1]));
}

// ---------------- init: build tf32 broadcast of initial h ----------------
__global__ void init_h_kernel(const float* __restrict__ init_state) {
    int i = blockIdx.x * blockDim.x + threadIdx.x;   // 2*NB*NH = 65536
    if (i < 2 * NB * NH) {
        int d = i >> 15;
        int b = (i >> 9) & 63;
        int k = i & 511;
        g_hTF[d][b][k] = f2tf_f(init_state[(size_t)b * (2 * NH) + d * NH + k]);
    }
}

// ---------------- xg precompute GEMM (tf32 tensor-core, 128x128x32) ----------------
constexpr int KT = 32;
constexpr int AS_LD = 36;
constexpr int BS_LD = 132;

__global__ __launch_bounds__(256, 2) void xg_gemm_tc(
    const float* __restrict__ x,
    const float* __restrict__ Wxf,
    const float* __restrict__ Wxb)
{
    __shared__ unsigned As[128][AS_LD];
    __shared__ unsigned Bs[KT][BS_LD];

    const int bn = blockIdx.x;
    const int bm = blockIdx.y;
    const int n0 = bn * 128;
    const int d  = n0 / (3 * NH);
    const int rr = n0 % (3 * NH);
    const int g  = rr / NH;
    const int h0 = rr % NH;
    const float* W = (d == 0 ? Wxf : Wxb) + (size_t)g * GK * NH + h0;
    const float* A = x + (size_t)bm * 128 * GK;

    const int tid  = threadIdx.x;
    const int warp = tid >> 5;
    const int lane = tid & 31;
    const int wm = warp & 1;
    const int wn = warp >> 1;
    const int g4 = lane >> 2;
    const int tg = lane & 3;

    float c[4][4][4];
    #pragma unroll
    for (int mi = 0; mi < 4; mi++)
        #pragma unroll
        for (int ni = 0; ni < 4; ni++)
            #pragma unroll
            for (int q = 0; q < 4; q++) c[mi][ni][q] = 0.f;

    for (int k0 = 0; k0 < GK; k0 += KT) {
        #pragma unroll
        for (int i = 0; i < 4; i++) {
            int slot = tid + i * 256;
            int row = slot >> 3, c4 = (slot & 7) * 4;
            float4 v = *(const float4*)(A + (size_t)row * GK + k0 + c4);
            As[row][c4 + 0] = f2tf(v.x);
            As[row][c4 + 1] = f2tf(v.y);
            As[row][c4 + 2] = f2tf(v.z);
            As[row][c4 + 3] = f2tf(v.w);
        }
        #pragma unroll
        for (int i = 0; i < 4; i++) {
            int slot = tid + i * 256;
            int kk = slot >> 5, c4 = (slot & 31) * 4;
            float4 v = *(const float4*)(W + (size_t)(k0 + kk) * NH + c4);
            Bs[kk][c4 + 0] = f2tf(v.x);
            Bs[kk][c4 + 1] = f2tf(v.y);
            Bs[kk][c4 + 2] = f2tf(v.z);
            Bs[kk][c4 + 3] = f2tf(v.w);
        }
        __syncthreads();

        #pragma unroll
        for (int ks = 0; ks < 4; ks++) {
            unsigned a[4][4], b[4][2];
            #pragma unroll
            for (int mi = 0; mi < 4; mi++) {
                int r = wm * 64 + mi * 16 + g4;
                int kc = ks * 8 + tg;
                a[mi][0] = As[r][kc];
                a[mi][1] = As[r + 8][kc];
                a[mi][2] = As[r][kc + 4];
                a[mi][3] = As[r + 8][kc + 4];
            }
            #pragma unroll
            for (int ni = 0; ni < 4; ni++) {
                int cc = wn * 32 + ni * 8 + g4;
                int kr = ks * 8 + tg;
                b[ni][0] = Bs[kr][cc];
                b[ni][1] = Bs[kr + 4][cc];
            }
            #pragma unroll
            for (int mi = 0; mi < 4; mi++)
                #pragma unroll
                for (int ni = 0; ni < 4; ni++)
                    mma_tf32(c[mi][ni], a[mi], b[ni]);
        }
        __syncthreads();
    }

    #pragma unroll
    for (int mi = 0; mi < 4; mi++) {
        #pragma unroll
        for (int half = 0; half < 2; half++) {
            int m = bm * 128 + wm * 64 + mi * 16 + g4 + half * 8;
            int s = m >> 6;
            int b = m & 63;
            size_t base = ((((size_t)d * SEQ + s) * 3 + g) * NB + b) * NH
                        + (h0 + wn * 32);
            #pragma unroll
            for (int ni = 0; ni < 4; ni++) {
                int col = ni * 8 + 2 * tg;
                float2 v;
                v.x = c[mi][ni][half * 2 + 0];
                v.y = c[mi][ni][half * 2 + 1];
                *(float2*)&g_xg[base + col] = v;
            }
        }
    }
}

// ---------------- grid barrier ----------------
__device__ __forceinline__ void grid_barrier(unsigned& gen) {
    __syncthreads();
    if (threadIdx.x == 0) {
        __threadfence();
        unsigned arrived = atomicAdd(&g_bar_cnt, 1u);
        if (arrived == RBLK - 1) {
            g_bar_cnt = 0;
            __threadfence();
            atomicAdd(&g_bar_gen, 1u);
        } else {
            while (*(volatile unsigned*)&g_bar_gen == gen) { __nanosleep(64); }
        }
        __threadfence();
        gen++;
    }
    __syncthreads();
}

// ---------------- persistent recurrent kernel (tensor-core) ----------------
constexpr int HLD = 516;
constexpr int OFF_RED2 = 64 * HLD;            // 33024
constexpr int OFF_XG2  = OFF_RED2 + 8 * 1088; // 41728
constexpr int OFF_T2   = OFF_XG2 + 1024;      // 42752
constexpr int OFF_U2   = OFF_T2 + 512;        // 43264
constexpr int OFF_HOLD = OFF_U2 + 512;        // 43776
constexpr int SMF2     = OFF_HOLD + 512;      // 44288
constexpr int SMEM_BYTES2 = SMF2 * 4;         // 177152

__device__ __forceinline__ float sigmoidf_(float x) {
    return 1.0f / (1.0f + __expf(-x));
}

__global__ __launch_bounds__(RT, 1) void gru_rec_tc(
    const float* __restrict__ Whf, const float* __restrict__ Whb,
    const float* __restrict__ bf,  const float* __restrict__ bb,
    const float* __restrict__ init_state,
    float* __restrict__ out)
{
    extern __shared__ __align__(16) float sm[];
    float*    smh    = sm;
    unsigned* smh_u  = (unsigned*)sm;
    float*    smred  = sm + OFF_RED2;
    float*    smxg   = sm + OFF_XG2;
    float*    smt    = sm + OFF_T2;
    float*    smu    = sm + OFF_U2;
    float*    smhold = sm + OFF_HOLD;

    const int bid = blockIdx.x;
    const int tid = threadIdx.x;
    const int d   = bid >> 6;
    const int c0  = (bid & 63) * COLS;
    const int warp = tid >> 5;
    const int lane = tid & 31;
    const int g4 = lane >> 2;
    const int tg = lane & 3;
    const int kbase = warp * 64;      // this warp's K slice
    const float* Wh   = d ? Whb : Whf;
    const float* bias = d ? bb  : bf;

    // ---- persistent B fragments (Wh columns c0..c0+7, this warp's K slice) ----
    unsigned bR[8][2], bU[8][2], bC[8][2];
    #pragma unroll
    for (int kk = 0; kk < 8; kk++) {
        int kr = kbase + kk * 8 + tg;
        bR[kk][0] = f2tf(Wh[(size_t)0 * NH * NH + (size_t)kr * NH + c0 + g4]);
        bR[kk][1] = f2tf(Wh[(size_t)0 * NH * NH + (size_t)(kr + 4) * NH + c0 + g4]);
        bU[kk][0] = f2tf(Wh[(size_t)1 * NH * NH + (size_t)kr * NH + c0 + g4]);
        bU[kk][1] = f2tf(Wh[(size_t)1 * NH * NH + (size_t)(kr + 4) * NH + c0 + g4]);
        bC[kk][0] = f2tf(Wh[(size_t)2 * NH * NH + (size_t)kr * NH + c0 + g4]);
        bC[kk][1] = f2tf(Wh[(size_t)2 * NH * NH + (size_t)(kr + 4) * NH + c0 + g4]);
    }
    // block-local fp32 h state for our columns: smhold[b*8+j]
    for (int i = tid; i < NB * COLS; i += RT) {
        int b = i >> 3, j = i & 7;
        smhold[i] = init_state[(size_t)b * (2 * NH) + d * NH + c0 + j];
    }
    unsigned gen = *(volatile unsigned*)&g_bar_gen;

    for (int t = 0; t < SEQ; t++) {
        const int sx = d ? (SEQ - 1 - t) : t;
        const float* xg_step = g_xg + (size_t)((size_t)d * SEQ + sx) * 3 * NB * NH;

        // ======== phase 1: r, u gates ========
        for (int idx = tid; idx < NB * NH / 4; idx += RT) {
            int row = idx >> 7, c4 = (idx & 127) << 2;
            *(float4*)&smh[row * HLD + c4] =
                __ldcg((const float4*)&g_hTF[d][row][c4]);
        }
        {
            int gb = tid >> 1;
            int g = gb >> 6, b = gb & 63, half = tid & 1;
            float4 v = *(const float4*)(xg_step + ((size_t)g * NB + b) * NH + c0 + half * 4);
            int gc = g * 8 + half * 4;
            smxg[(gc + 0) * 64 + b] = v.x;
            smxg[(gc + 1) * 64 + b] = v.y;
            smxg[(gc + 2) * 64 + b] = v.z;
            smxg[(gc + 3) * 64 + b] = v.w;
        }
        __syncthreads();
        {
            float acc[4][2][4];
            #pragma unroll
            for (int mi = 0; mi < 4; mi++)
                #pragma unroll
                for (int ni = 0; ni < 2; ni++)
                    #pragma unroll
                    for (int q = 0; q < 4; q++) acc[mi][ni][q] = 0.f;
            #pragma unroll
            for (int kk = 0; kk < 8; kk++) {
                int kc = kbase + kk * 8 + tg;
                unsigned a[4][4];
                #pragma unroll
                for (int mi = 0; mi < 4; mi++) {
                    int r = mi * 16 + g4;
                    a[mi][0] = smh_u[r * HLD + kc];
                    a[mi][1] = smh_u[(r + 8) * HLD + kc];
                    a[mi][2] = smh_u[r * HLD + kc + 4];
                    a[mi][3] = smh_u[(r + 8) * HLD + kc + 4];
                }
                #pragma unroll
                for (int mi = 0; mi < 4; mi++) {
                    mma_tf32(acc[mi][0], a[mi], bR[kk]);
                    mma_tf32(acc[mi][1], a[mi], bU[kk]);
                }
            }
            #pragma unroll
            for (int mi = 0; mi < 4; mi++)
                #pragma unroll
                for (int ni = 0; ni < 2; ni++) {
                    int b = mi * 16 + g4;
                    int gc = ni * 8 + 2 * tg;
                    smred[warp * 1088 + gc * 68 + b]           = acc[mi][ni][0];
                    smred[warp * 1088 + (gc + 1) * 68 + b]     = acc[mi][ni][1];
                    smred[warp * 1088 + gc * 68 + b + 8]       = acc[mi][ni][2];
                    smred[warp * 1088 + (gc + 1) * 68 + b + 8] = acc[mi][ni][3];
                }
        }
        __syncthreads();
        for (int o = tid; o < 1024; o += RT) {
            int gc = o >> 6, b = o & 63;
            float s = 0.f;
            #pragma unroll
            for (int q = 0; q < 8; q++) s += smred[q * 1088 + gc * 68 + b];
            int g = gc >> 3, j = gc & 7, col = c0 + j;
            float pre = s + smxg[gc * 64 + b] + bias[g * NH + col];
            float v = sigmoidf_(pre);
            if (g == 0) {
                smt[b * 8 + j] = f2tf_f(v * smhold[b * 8 + j]);   // r*h (tf32)
            } else {
                smu[j * 64 + b] = v;                               // u (block-local)
            }
        }
        __syncthreads();
        if (tid < 128) {
            int b = tid >> 1, half = tid & 1;
            __stcg((float4*)&g_rhTF[d][b][c0 + half * 4],
                   *(const float4*)&smt[b * 8 + half * 4]);
        }
        grid_barrier(gen);

        // ======== phase 2: candidate + update ========
        for (int idx = tid; idx < NB * NH / 4; idx += RT) {
            int row = idx >> 7, c4 = (idx & 127) << 2;
            *(float4*)&smh[row * HLD + c4] =
                __ldcg((const float4*)&g_rhTF[d][row][c4]);
        }
        if (tid < 128) {
            int b = tid >> 1, half = tid & 1;
            float4 v = *(const float4*)(xg_step + ((size_t)2 * NB + b) * NH + c0 + half * 4);
            int gc = half * 4;
            smxg[(gc + 0) * 64 + b] = v.x;
            smxg[(gc + 1) * 64 + b] = v.y;
            smxg[(gc + 2) * 64 + b] = v.z;
            smxg[(gc + 3) * 64 + b] = v.w;
        }
        __syncthreads();
        {
            float acc[4][4];
            #pragma unroll
            for (int mi = 0; mi < 4; mi++)
                #pragma unroll
                for (int q = 0; q < 4; q++) acc[mi][q] = 0.f;
            #pragma unroll
            for (int kk = 0; kk < 8; kk++) {
                int kc = kbase + kk * 8 + tg;
                unsigned a[4][4];
                #pragma unroll
                for (int mi = 0; mi < 4; mi++) {
                    int r = mi * 16 + g4;
                    a[mi][0] = smh_u[r * HLD + kc];
                    a[mi][1] = smh_u[(r + 8) * HLD + kc];
                    a[mi][2] = smh_u[r * HLD + kc + 4];
                    a[mi][3] = smh_u[(r + 8) * HLD + kc + 4];
                }
                #pragma unroll
                for (int mi = 0; mi < 4; mi++)
                    mma_tf32(acc[mi], a[mi], bC[kk]);
            }
            #pragma unroll
            for (int mi = 0; mi < 4; mi++) {
                int b = mi * 16 + g4;
                int gc = 2 * tg;
                smred[warp * 544 + gc * 68 + b]           = acc[mi][0];
                smred[warp * 544 + (gc + 1) * 68 + b]     = acc[mi][1];
                smred[warp * 544 + gc * 68 + b + 8]       = acc[mi][2];
                smred[warp * 544 + (gc + 1) * 68 + b + 8] = acc[mi][3];
            }
        }
        __syncthreads();
        for (int o = tid; o < 512; o += RT) {
            int j = o >> 6, b = o & 63, col = c0 + j;
            float s = 0.f;
            #pragma unroll
            for (int q = 0; q < 8; q++) s += smred[q * 544 + j * 68 + b];
            float pre = s + smxg[j * 64 + b] + bias[2 * NH + col];
            float c = tanhf(pre);
            float u = smu[j * 64 + b];
            float hold = smhold[b * 8 + j];
            float hn = u * hold + (1.0f - u) * c;
            smt[b * 8 + j] = hn;
            if (t == SEQ - 1) {
                out[(size_t)SEQ * (NB * 2 * NH) + (size_t)b * (2 * NH) + d * NH + col] = hn;
            }
        }
        __syncthreads();
        {
            const int srow = d ? (SEQ - 1 - t) : t;
            if (tid < 128) {
                int b = tid >> 1, half = tid & 1;
                float4 v = *(const float4*)&smt[b * 8 + half * 4];
                *(float4*)&smhold[b * 8 + half * 4] = v;
                *(float4*)&out[(size_t)srow * (NB * 2 * NH) + (size_t)b * (2 * NH)
                               + d * NH + c0 + half * 4] = v;
                float4 vt;
                vt.x = f2tf_f(v.x); vt.y = f2tf_f(v.y);
                vt.z = f2tf_f(v.z); vt.w = f2tf_f(v.w);
                __stcg((float4*)&g_hTF[d][b][c0 + half * 4], vt);
            }
        }
        grid_barrier(gen);
    }
}

// ---------------- launch ----------------
extern "C" void kernel_launch(void* const* d_in, const int* in_sizes, int n_in,
                              void* d_out, int out_size) {
    const float* x    = (const float*)d_in[0];
    const float* init = (const float*)d_in[1];
    const float* Wxf  = (const float*)d_in[2];
    const float* Whf  = (const float*)d_in[3];
    const float* bf   = (const float*)d_in[4];
    const float* Wxb  = (const float*)d_in[5];
    const float* Whb  = (const float*)d_in[6];
    const float* bb   = (const float*)d_in[7];
    float* out = (float*)d_out;

    cudaFuncSetAttribute(gru_rec_tc,
                         cudaFuncAttributeMaxDynamicSharedMemorySize, SMEM_BYTES2);

    init_h_kernel<<<(2 * NB * NH + 255) / 256, 256>>>(init);
    xg_gemm_tc<<<dim3(GN / 128, GM / 128), 256>>>(x, Wxf, Wxb);
    gru_rec_tc<<<RBLK, RT, SMEM_BYTES2>>>(Whf, Whb, bf, bb, init, out);
}